// round 6
// baseline (speedup 1.0000x reference)
#include <cuda_runtime.h>
#include <cuda_bf16.h>

// ---------------- problem constants ----------------
#define CK     2304
#define HW     16384
#define FDIM   256
#define NROI   8192

// ---------------- GEMM config ----------------
#define BM     128
#define BN     64
#define BK     32
#define NIT    (CK / BK)        // 72 (even)
#define NTHR   256

#define APITCH 80               // bytes per smem row: 20 words -> ldmatrix conflict-free
#define ATILE  (128 * APITCH)   // 10240
#define BTILE  (64 * APITCH)    // 5120
#define BH_OFF (2 * ATILE)
#define BL_OFF (2 * ATILE + BTILE)
#define STAGE  (2 * ATILE + 2 * BTILE)   // 30720
#define NSTAGE 3
#define SMEM_BYTES (NSTAGE * STAGE)      // 92160 -> 2 CTAs/SM = 184320

// device scratch (allocation-free)
__device__ __nv_bfloat16 g_whi[FDIM * CK];
__device__ __nv_bfloat16 g_wlo[FDIM * CK];
__device__ unsigned      g_xpk[256 * HW];   // packed {hi16, lo16<<16} of x

// ---------------- PTX helpers ----------------
__device__ __forceinline__ unsigned smem_u32(const void* p) {
    unsigned a;
    asm("{ .reg .u64 t; cvta.to.shared.u64 t, %1; cvt.u32.u64 %0, t; }" : "=r"(a) : "l"(p));
    return a;
}
#define LDSM4(r, a)                                                             \
    asm volatile("ldmatrix.sync.aligned.m8n8.x4.shared.b16 {%0,%1,%2,%3}, [%4];"\
        : "=r"((r)[0]), "=r"((r)[1]), "=r"((r)[2]), "=r"((r)[3]) : "r"(a))
#define MMA16816(c, a, b0, b1)                                                  \
    asm volatile("mma.sync.aligned.m16n8k16.row.col.f32.bf16.bf16.f32 "         \
        "{%0,%1,%2,%3}, {%4,%5,%6,%7}, {%8,%9}, {%0,%1,%2,%3};"                 \
        : "+f"((c)[0]), "+f"((c)[1]), "+f"((c)[2]), "+f"((c)[3])                \
        : "r"((a)[0]), "r"((a)[1]), "r"((a)[2]), "r"((a)[3]), "r"(b0), "r"(b1))
#define STS64(addr, v0, v1)                                                     \
    asm volatile("st.shared.v2.b32 [%0], {%1,%2};" :: "r"(addr), "r"(v0), "r"(v1) : "memory")
#define CPASYNC16(dst, src)                                                     \
    asm volatile("cp.async.cg.shared.global [%0], [%1], 16;" :: "r"(dst), "l"(src))
#define CPCOMMIT() asm volatile("cp.async.commit_group;" ::: "memory")
#define CPWAIT(n)  asm volatile("cp.async.wait_group %0;" :: "n"(n) : "memory")

// ---------------------------------------------------------------------------
// prep: wsplit + xpack + bias fill fused (block-range dispatch)
// ---------------------------------------------------------------------------
#define WBLK 1152     // 589824 / 512
#define XBLK 8192     // 4194304 / 512
#define OBLK 2048     // 1048576 float4 / 512
__global__ __launch_bounds__(512) void prep_kernel(
    const float* __restrict__ w, const float* __restrict__ x,
    const float* __restrict__ bias, float4* __restrict__ out4)
{
    int b = blockIdx.x, t = threadIdx.x;
    if (b < WBLK) {
        int i = b * 512 + t;
        float v = w[i];
        __nv_bfloat16 hi = __float2bfloat16(v);
        g_whi[i] = hi;
        g_wlo[i] = __float2bfloat16(v - __bfloat162float(hi));
    } else if (b < WBLK + XBLK) {
        int i = (b - WBLK) * 512 + t;
        float v = x[i];
        __nv_bfloat16 hi = __float2bfloat16(v);
        __nv_bfloat16 lo = __float2bfloat16(v - __bfloat162float(hi));
        unsigned h = *(unsigned short*)&hi, l = *(unsigned short*)&lo;
        g_xpk[i] = h | (l << 16);
    } else {
        int i = (b - WBLK - XBLK) * 512 + t;
        float bv = __ldg(&bias[i >> 12]);
        out4[i] = make_float4(bv, bv, bv, bv);
    }
}

// ---------------------------------------------------------------------------
// main: bf16x3 sparse-im2col GEMM via mma.sync m16n8k16
// 3-stage smem pipeline; gather LDGs issued 2 iterations ahead of their STS.
// ---------------------------------------------------------------------------
__global__ __launch_bounds__(NTHR, 2) void conv_mma(
    const float* __restrict__ bias, const int* __restrict__ roi,
    float* __restrict__ out)
{
    extern __shared__ char sm[];
    __shared__ int sh_p[BN];
    const unsigned smbase = smem_u32(sm);

    const int tid = threadIdx.x, lane = tid & 31, wid = tid >> 5;
    const int n0 = blockIdx.x * BN, m0g = blockIdx.y * BM;

    if (tid < BN) sh_p[tid] = __ldg(&roi[n0 + tid]);
    __syncthreads();

    const int gn = tid & 63;
    const int gkq0 = tid >> 6;            // 0..3
    const int gp = sh_p[gn];
    const int gh = gp >> 7, gw = gp & 127;

    const int wm = (wid >> 1) * 32, wn = (wid & 1) * 32;
    const int l8 = lane & 7;
    const unsigned a_lane_off =
        (unsigned)((wm + ((lane >> 3) & 1) * 8 + l8) * APITCH + ((lane >> 4) * 8) * 2);
    const unsigned b_lane_off =
        (unsigned)((wn + (lane >> 4) * 8 + l8) * APITCH + (((lane >> 3) & 1) * 8) * 2);

    float acc[2][4][4];
#pragma unroll
    for (int a = 0; a < 2; a++)
#pragma unroll
        for (int b = 0; b < 4; b++)
#pragma unroll
            for (int c = 0; c < 4; c++) acc[a][b][c] = 0.0f;

    unsigned pkE[2][4], pkO[2][4];   // gather reg buffers (even / odd chunks)

    // ---- loaders ----
    auto issue_A = [&](int it, int st) {
        const int k0 = it * BK;
        const unsigned dst0 = smbase + st * STAGE;
#pragma unroll
        for (int r = 0; r < 4; r++) {
            int c2 = r * NTHR + tid;
            int half = c2 >> 9, m = (c2 >> 2) & 127, q = c2 & 3;
            const __nv_bfloat16* src =
                (half ? g_wlo : g_whi) + (m0g + m) * CK + k0 + q * 8;
            CPASYNC16(dst0 + half * ATILE + m * APITCH + q * 16, src);
        }
    };
    auto gather = [&](int it, unsigned (&pk)[2][4]) {
        const int k0 = it * BK;
#pragma unroll
        for (int r = 0; r < 2; r++) {
            const int kq = gkq0 + r * 4;
#pragma unroll
            for (int j = 0; j < 4; j++) {
                int kk = k0 + kq * 4 + j;
                unsigned c = ((unsigned)kk * 7282u) >> 16;     // kk/9
                int s9 = kk - (int)c * 9;
                int di = (s9 * 11) >> 5;                       // s9/3
                int dj = s9 - di * 3;
                int hh = gh + di - 1, ww = gw + dj - 1;
                unsigned v = 0u;
                if ((unsigned)hh < 128u && (unsigned)ww < 128u)
                    v = __ldg(&g_xpk[(int)c * HW + hh * 128 + ww]);
                pk[r][j] = v;
            }
        }
    };
    auto store_B = [&](int st, unsigned (&pk)[2][4]) {
        const unsigned dst0 = smbase + st * STAGE;
#pragma unroll
        for (int r = 0; r < 2; r++) {
            const int kq = gkq0 + r * 4;
            unsigned hp0 = __byte_perm(pk[r][0], pk[r][1], 0x5410);
            unsigned hp1 = __byte_perm(pk[r][2], pk[r][3], 0x5410);
            unsigned lp0 = __byte_perm(pk[r][0], pk[r][1], 0x7632);
            unsigned lp1 = __byte_perm(pk[r][2], pk[r][3], 0x7632);
            unsigned off = (unsigned)(gn * APITCH + kq * 8);
            STS64(dst0 + BH_OFF + off, hp0, hp1);
            STS64(dst0 + BL_OFF + off, lp0, lp1);
        }
    };
    auto compute = [&](int st) {
        const unsigned base = smbase + st * STAGE;
#pragma unroll
        for (int k16 = 0; k16 < 2; k16++) {
            unsigned ah[2][4], al[2][4];
#pragma unroll
            for (int mt = 0; mt < 2; mt++) {
                unsigned addr = base + a_lane_off + mt * 16 * APITCH + k16 * 32;
                LDSM4(ah[mt], addr);
                LDSM4(al[mt], addr + ATILE);
            }
            unsigned bh[2][4], bl[2][4];
#pragma unroll
            for (int np = 0; np < 2; np++) {
                unsigned addr = base + BH_OFF + b_lane_off + np * 16 * APITCH + k16 * 32;
                LDSM4(bh[np], addr);
                LDSM4(bl[np], addr + BTILE);
            }
#pragma unroll
            for (int mt = 0; mt < 2; mt++)
#pragma unroll
                for (int nt = 0; nt < 4; nt++) {
                    int np = nt >> 1, s = (nt & 1) * 2;
                    MMA16816(acc[mt][nt], ah[mt], bh[np][s], bh[np][s + 1]);
                    MMA16816(acc[mt][nt], al[mt], bh[np][s], bh[np][s + 1]);
                    MMA16816(acc[mt][nt], ah[mt], bl[np][s], bl[np][s + 1]);
                }
        }
    };

    // one pipeline step (it: chunk being computed; cur: its smem stage)
    auto body = [&](int it, int cur, unsigned (&src)[2][4], unsigned (&dst)[2][4]) {
        int n1 = cur + 1; if (n1 == NSTAGE) n1 = 0;
        int n2 = n1 + 1;  if (n2 == NSTAGE) n2 = 0;
        if (it + 2 < NIT) issue_A(it + 2, n2);
        CPCOMMIT();                               // always: keeps group count uniform
        if (it + 1 < NIT) store_B(n1, src);       // STS of chunk it+1 (gathered last iter)
        if (it + 2 < NIT) gather(it + 2, dst);    // LDGs land ~2 iterations from use
        CPWAIT(2);                                // A(it) resident
        compute(cur);
        __syncthreads();
    };

    // ---- prologue ----
    issue_A(0, 0); CPCOMMIT();
    issue_A(1, 1); CPCOMMIT();
    gather(0, pkE);
    store_B(0, pkE);
    gather(1, pkO);
    CPWAIT(1);                                    // A(0) resident
    __syncthreads();

    // ---- mainloop: unrolled by 2 so pk buffers stay in registers ----
    int cur = 0;
    for (int itb = 0; itb < NIT; itb += 2) {
        body(itb, cur, pkO, pkE);                 // even it: store odd chunk, gather even
        int c1 = cur + 1; if (c1 == NSTAGE) c1 = 0;
        body(itb + 1, c1, pkE, pkO);              // odd it: store even chunk, gather odd
        cur = c1 + 1; if (cur == NSTAGE) cur = 0;
    }

    // ---- epilogue: scatter acc + bias ----
#pragma unroll
    for (int mt = 0; mt < 2; mt++) {
        const int f0 = m0g + wm + mt * 16 + (lane >> 2);
        const float b0 = __ldg(&bias[f0]);
        const float b1 = __ldg(&bias[f0 + 8]);
        float* o0 = out + f0 * HW;
        float* o1 = out + (f0 + 8) * HW;
#pragma unroll
        for (int nt = 0; nt < 4; nt++) {
            const int nl = wn + nt * 8 + 2 * (lane & 3);
            const int p0 = sh_p[nl], p1 = sh_p[nl + 1];
            o0[p0] = acc[mt][nt][0] + b0;
            o0[p1] = acc[mt][nt][1] + b0;
            o1[p0] = acc[mt][nt][2] + b1;
            o1[p1] = acc[mt][nt][3] + b1;
        }
    }
}

// ---------------------------------------------------------------------------
extern "C" void kernel_launch(void* const* d_in, const int* in_sizes, int n_in,
                              void* d_out, int out_size)
{
    const float* x   = (const float*)d_in[0];
    const float* w   = (const float*)d_in[1];
    const float* b   = (const float*)d_in[2];
    const int*   roi = (const int*)d_in[3];
    float*       out = (float*)d_out;

    cudaFuncSetAttribute(conv_mma,
                         cudaFuncAttributeMaxDynamicSharedMemorySize, SMEM_BYTES);

    prep_kernel<<<WBLK + XBLK + OBLK, 512>>>(w, x, b, (float4*)out);

    dim3 grid(NROI / BN, FDIM / BM);    // (128, 2)
    conv_mma<<<grid, NTHR, SMEM_BYTES>>>(b, roi, out);
}

// round 7
// speedup vs baseline: 1.0898x; 1.0898x over previous
#include <cuda_runtime.h>
#include <cuda_bf16.h>

// ---------------- problem constants ----------------
#define CK     2304
#define HW     16384
#define FDIM   256
#define NROI   8192

// ---------------- GEMM config ----------------
#define BM     128
#define BN     64
#define BK     32
#define NIT    (CK / BK)        // 72
#define NTHR   256

#define APITCH 80               // bytes per smem row: 20 words -> ldmatrix conflict-free
#define ATILE  (128 * APITCH)   // 10240
#define BTILE  (64 * APITCH)    // 5120
#define BH_OFF (2 * ATILE)
#define BL_OFF (2 * ATILE + BTILE)
#define STAGE  (2 * ATILE + 2 * BTILE)   // 30720
#define SMEM_BYTES (2 * STAGE)           // 61440 -> 2 CTAs/SM

// device scratch (allocation-free)
__device__ __nv_bfloat16 g_whi[FDIM * CK];
__device__ __nv_bfloat16 g_wlo[FDIM * CK];
__device__ unsigned      g_xpk[256 * HW];   // packed {hi16, lo16<<16} of x

// ---------------- PTX helpers ----------------
__device__ __forceinline__ unsigned smem_u32(const void* p) {
    unsigned a;
    asm("{ .reg .u64 t; cvta.to.shared.u64 t, %1; cvt.u32.u64 %0, t; }" : "=r"(a) : "l"(p));
    return a;
}
#define LDSM4(r, a)                                                             \
    asm volatile("ldmatrix.sync.aligned.m8n8.x4.shared.b16 {%0,%1,%2,%3}, [%4];"\
        : "=r"((r)[0]), "=r"((r)[1]), "=r"((r)[2]), "=r"((r)[3]) : "r"(a))
// NOTE: non-volatile — pure register dataflow; lets ptxas schedule MMAs freely.
#define MMA16816(c, a, b0, b1)                                                  \
    asm("mma.sync.aligned.m16n8k16.row.col.f32.bf16.bf16.f32 "                  \
        "{%0,%1,%2,%3}, {%4,%5,%6,%7}, {%8,%9}, {%0,%1,%2,%3};"                 \
        : "+f"((c)[0]), "+f"((c)[1]), "+f"((c)[2]), "+f"((c)[3])                \
        : "r"((a)[0]), "r"((a)[1]), "r"((a)[2]), "r"((a)[3]), "r"(b0), "r"(b1))
#define STS64(addr, v0, v1)                                                     \
    asm volatile("st.shared.v2.b32 [%0], {%1,%2};" :: "r"(addr), "r"(v0), "r"(v1) : "memory")
#define CPASYNC16(dst, src)                                                     \
    asm volatile("cp.async.cg.shared.global [%0], [%1], 16;" :: "r"(dst), "l"(src))
#define CPCOMMIT() asm volatile("cp.async.commit_group;" ::: "memory")
#define CPWAIT0()  asm volatile("cp.async.wait_group 0;"  ::: "memory")

// ---------------------------------------------------------------------------
// prep: wsplit + xpack + bias fill fused (block-range dispatch)
// ---------------------------------------------------------------------------
#define WBLK 1152     // 589824 / 512
#define XBLK 8192     // 4194304 / 512
#define OBLK 2048     // 1048576 float4 / 512
__global__ __launch_bounds__(512) void prep_kernel(
    const float* __restrict__ w, const float* __restrict__ x,
    const float* __restrict__ bias, float4* __restrict__ out4)
{
    int b = blockIdx.x, t = threadIdx.x;
    if (b < WBLK) {
        int i = b * 512 + t;
        float v = w[i];
        __nv_bfloat16 hi = __float2bfloat16(v);
        g_whi[i] = hi;
        g_wlo[i] = __float2bfloat16(v - __bfloat162float(hi));
    } else if (b < WBLK + XBLK) {
        int i = (b - WBLK) * 512 + t;
        float v = x[i];
        __nv_bfloat16 hi = __float2bfloat16(v);
        __nv_bfloat16 lo = __float2bfloat16(v - __bfloat162float(hi));
        unsigned h = *(unsigned short*)&hi, l = *(unsigned short*)&lo;
        g_xpk[i] = h | (l << 16);
    } else {
        int i = (b - WBLK - XBLK) * 512 + t;
        float bv = __ldg(&bias[i >> 12]);
        out4[i] = make_float4(bv, bv, bv, bv);
    }
}

// ---------------------------------------------------------------------------
// main: bf16x3 sparse-im2col GEMM via mma.sync m16n8k16
// BM=128 x BN=64; 8 warps as 4(m) x 2(n) -> 32x32 per warp; 2 CTAs/SM.
// MMAs issued term-major: 8 independent accumulators between RAW-dependent ops.
// ---------------------------------------------------------------------------
__global__ __launch_bounds__(NTHR, 2) void conv_mma(
    const float* __restrict__ bias, const int* __restrict__ roi,
    float* __restrict__ out)
{
    extern __shared__ char sm[];
    __shared__ int sh_p[BN];
    const unsigned smbase = smem_u32(sm);

    const int tid = threadIdx.x, lane = tid & 31, wid = tid >> 5;
    const int n0 = blockIdx.x * BN, m0g = blockIdx.y * BM;

    if (tid < BN) sh_p[tid] = __ldg(&roi[n0 + tid]);
    __syncthreads();

    const int gn = tid & 63;
    const int gkq0 = tid >> 6;            // 0..3
    const int gp = sh_p[gn];
    const int gh = gp >> 7, gw = gp & 127;

    const int wm = (wid >> 1) * 32, wn = (wid & 1) * 32;
    const int l8 = lane & 7;
    const unsigned a_lane_off =
        (unsigned)((wm + ((lane >> 3) & 1) * 8 + l8) * APITCH + ((lane >> 4) * 8) * 2);
    const unsigned b_lane_off =
        (unsigned)((wn + (lane >> 4) * 8 + l8) * APITCH + (((lane >> 3) & 1) * 8) * 2);

    float acc[2][4][4];
#pragma unroll
    for (int a = 0; a < 2; a++)
#pragma unroll
        for (int b = 0; b < 4; b++)
#pragma unroll
            for (int c = 0; c < 4; c++) acc[a][b][c] = 0.0f;

    unsigned pk[2][4];

    // ---- stage loaders ----
    auto issue_A = [&](int it, int st) {
        const int k0 = it * BK;
        const unsigned dst0 = smbase + st * STAGE;
#pragma unroll
        for (int r = 0; r < 4; r++) {
            int c2 = r * NTHR + tid;
            int half = c2 >> 9, m = (c2 >> 2) & 127, q = c2 & 3;
            const __nv_bfloat16* src =
                (half ? g_wlo : g_whi) + (m0g + m) * CK + k0 + q * 8;
            CPASYNC16(dst0 + half * ATILE + m * APITCH + q * 16, src);
        }
    };
    auto issue_B = [&](int it) {
        const int k0 = it * BK;
#pragma unroll
        for (int r = 0; r < 2; r++) {
            const int kq = gkq0 + r * 4;
#pragma unroll
            for (int j = 0; j < 4; j++) {
                int kk = k0 + kq * 4 + j;
                unsigned c = ((unsigned)kk * 7282u) >> 16;     // kk/9
                int s9 = kk - (int)c * 9;
                int di = (s9 * 11) >> 5;                       // s9/3
                int dj = s9 - di * 3;
                int hh = gh + di - 1, ww = gw + dj - 1;
                unsigned v = 0u;
                if ((unsigned)hh < 128u && (unsigned)ww < 128u)
                    v = __ldg(&g_xpk[(int)c * HW + hh * 128 + ww]);
                pk[r][j] = v;
            }
        }
    };
    auto store_B = [&](int st) {
        const unsigned dst0 = smbase + st * STAGE;
#pragma unroll
        for (int r = 0; r < 2; r++) {
            const int kq = gkq0 + r * 4;
            unsigned hp0 = __byte_perm(pk[r][0], pk[r][1], 0x5410);
            unsigned hp1 = __byte_perm(pk[r][2], pk[r][3], 0x5410);
            unsigned lp0 = __byte_perm(pk[r][0], pk[r][1], 0x7632);
            unsigned lp1 = __byte_perm(pk[r][2], pk[r][3], 0x7632);
            unsigned off = (unsigned)(gn * APITCH + kq * 8);
            STS64(dst0 + BH_OFF + off, hp0, hp1);
            STS64(dst0 + BL_OFF + off, lp0, lp1);
        }
    };
    auto compute = [&](int st) {
        const unsigned base = smbase + st * STAGE;
#pragma unroll
        for (int k16 = 0; k16 < 2; k16++) {
            // ---- load all fragments for this k16 first ----
            unsigned ah[2][4], al[2][4];
#pragma unroll
            for (int mt = 0; mt < 2; mt++) {
                unsigned addr = base + a_lane_off + mt * 16 * APITCH + k16 * 32;
                LDSM4(ah[mt], addr);
                LDSM4(al[mt], addr + ATILE);
            }
            unsigned bh[2][4], bl[2][4];
#pragma unroll
            for (int np = 0; np < 2; np++) {
                unsigned addr = base + BH_OFF + b_lane_off + np * 16 * APITCH + k16 * 32;
                LDSM4(bh[np], addr);
                LDSM4(bl[np], addr + BTILE);
            }
            // ---- term-major MMA issue: 8 independent accs per term ----
#pragma unroll
            for (int mt = 0; mt < 2; mt++)
#pragma unroll
                for (int nt = 0; nt < 4; nt++) {
                    int np = nt >> 1, s = (nt & 1) * 2;
                    MMA16816(acc[mt][nt], ah[mt], bh[np][s], bh[np][s + 1]);
                }
#pragma unroll
            for (int mt = 0; mt < 2; mt++)
#pragma unroll
                for (int nt = 0; nt < 4; nt++) {
                    int np = nt >> 1, s = (nt & 1) * 2;
                    MMA16816(acc[mt][nt], al[mt], bh[np][s], bh[np][s + 1]);
                }
#pragma unroll
            for (int mt = 0; mt < 2; mt++)
#pragma unroll
                for (int nt = 0; nt < 4; nt++) {
                    int np = nt >> 1, s = (nt & 1) * 2;
                    MMA16816(acc[mt][nt], ah[mt], bl[np][s], bl[np][s + 1]);
                }
        }
    };

    // ---- prologue ----
    issue_A(0, 0);
    CPCOMMIT();
    issue_B(0);
    store_B(0);
    CPWAIT0();
    __syncthreads();

    // ---- mainloop (double-buffered, round-5 structure) ----
    for (int it = 0; it < NIT; it++) {
        const int cur = it & 1, nxt = cur ^ 1;
        const bool more = (it + 1) < NIT;
        if (more) {
            issue_A(it + 1, nxt);
            CPCOMMIT();
            issue_B(it + 1);
        }
        compute(cur);
        if (more) {
            store_B(nxt);
            CPWAIT0();
        }
        __syncthreads();
    }

    // ---- epilogue: scatter acc + bias ----
#pragma unroll
    for (int mt = 0; mt < 2; mt++) {
        const int f0 = m0g + wm + mt * 16 + (lane >> 2);
        const float b0 = __ldg(&bias[f0]);
        const float b1 = __ldg(&bias[f0 + 8]);
        float* o0 = out + f0 * HW;
        float* o1 = out + (f0 + 8) * HW;
#pragma unroll
        for (int nt = 0; nt < 4; nt++) {
            const int nl = wn + nt * 8 + 2 * (lane & 3);
            const int p0 = sh_p[nl], p1 = sh_p[nl + 1];
            o0[p0] = acc[mt][nt][0] + b0;
            o0[p1] = acc[mt][nt][1] + b0;
            o1[p0] = acc[mt][nt][2] + b1;
            o1[p1] = acc[mt][nt][3] + b1;
        }
    }
}

// ---------------------------------------------------------------------------
extern "C" void kernel_launch(void* const* d_in, const int* in_sizes, int n_in,
                              void* d_out, int out_size)
{
    const float* x   = (const float*)d_in[0];
    const float* w   = (const float*)d_in[1];
    const float* b   = (const float*)d_in[2];
    const int*   roi = (const int*)d_in[3];
    float*       out = (float*)d_out;

    cudaFuncSetAttribute(conv_mma,
                         cudaFuncAttributeMaxDynamicSharedMemorySize, SMEM_BYTES);

    prep_kernel<<<WBLK + XBLK + OBLK, 512>>>(w, x, b, (float4*)out);

    dim3 grid(NROI / BN, FDIM / BM);    // (128, 2)
    conv_mma<<<grid, NTHR, SMEM_BYTES>>>(b, roi, out);
}

// round 8
// speedup vs baseline: 1.0935x; 1.0034x over previous
#include <cuda_runtime.h>
#include <cuda_bf16.h>

// ---------------- problem constants ----------------
#define CK     2304
#define HW     16384
#define FDIM   256
#define NROI   8192
#define PW     130          // padded width/height
#define PCH    16900        // 130*130 per channel

// ---------------- GEMM config ----------------
#define BM     128
#define BN     64
#define BK     32
#define NIT    (CK / BK)        // 72
#define NTHR   256

#define APITCH 80               // bytes per smem row: 20 words -> ldmatrix conflict-free
#define ATILE  (128 * APITCH)   // 10240
#define BTILE  (64 * APITCH)    // 5120
#define BH_OFF (2 * ATILE)
#define BL_OFF (2 * ATILE + BTILE)
#define STAGE  (2 * ATILE + 2 * BTILE)   // 30720
#define OTBL_OFF (2 * STAGE)             // offset table after the 2 stages
#define SMEM_BYTES (2 * STAGE + CK * 4)  // 61440 + 9216 = 70656 -> 2 CTAs/SM

// device scratch (allocation-free)
__device__ __nv_bfloat16 g_whi[FDIM * CK];
__device__ __nv_bfloat16 g_wlo[FDIM * CK];
__device__ unsigned      g_xpk[256 * PCH];   // padded, packed {hi16, lo16<<16} of x

// ---------------- PTX helpers ----------------
__device__ __forceinline__ unsigned smem_u32(const void* p) {
    unsigned a;
    asm("{ .reg .u64 t; cvta.to.shared.u64 t, %1; cvt.u32.u64 %0, t; }" : "=r"(a) : "l"(p));
    return a;
}
#define LDSM4(r, a)                                                             \
    asm volatile("ldmatrix.sync.aligned.m8n8.x4.shared.b16 {%0,%1,%2,%3}, [%4];"\
        : "=r"((r)[0]), "=r"((r)[1]), "=r"((r)[2]), "=r"((r)[3]) : "r"(a))
#define MMA16816(c, a, b0, b1)                                                  \
    asm("mma.sync.aligned.m16n8k16.row.col.f32.bf16.bf16.f32 "                  \
        "{%0,%1,%2,%3}, {%4,%5,%6,%7}, {%8,%9}, {%0,%1,%2,%3};"                 \
        : "+f"((c)[0]), "+f"((c)[1]), "+f"((c)[2]), "+f"((c)[3])                \
        : "r"((a)[0]), "r"((a)[1]), "r"((a)[2]), "r"((a)[3]), "r"(b0), "r"(b1))
#define STS64(addr, v0, v1)                                                     \
    asm volatile("st.shared.v2.b32 [%0], {%1,%2};" :: "r"(addr), "r"(v0), "r"(v1) : "memory")
#define CPASYNC16(dst, src)                                                     \
    asm volatile("cp.async.cg.shared.global [%0], [%1], 16;" :: "r"(dst), "l"(src))
#define CPCOMMIT() asm volatile("cp.async.commit_group;" ::: "memory")
#define CPWAIT0()  asm volatile("cp.async.wait_group 0;"  ::: "memory")

// ---------------------------------------------------------------------------
// prep: wsplit + xpack(padded) + border zero + bias fill (block-range dispatch)
// ---------------------------------------------------------------------------
#define WBLK 1152     // 589824 / 512
#define XBLK 8192     // 4194304 / 512
#define PBLK 258      // 132096 border cells / 512
#define OBLK 2048     // 1048576 float4 / 512
__global__ __launch_bounds__(512) void prep_kernel(
    const float* __restrict__ w, const float* __restrict__ x,
    const float* __restrict__ bias, float4* __restrict__ out4)
{
    int b = blockIdx.x, t = threadIdx.x;
    if (b < WBLK) {
        int i = b * 512 + t;
        float v = w[i];
        __nv_bfloat16 hi = __float2bfloat16(v);
        g_whi[i] = hi;
        g_wlo[i] = __float2bfloat16(v - __bfloat162float(hi));
    } else if (b < WBLK + XBLK) {
        int i = (b - WBLK) * 512 + t;
        float v = x[i];
        __nv_bfloat16 hi = __float2bfloat16(v);
        __nv_bfloat16 lo = __float2bfloat16(v - __bfloat162float(hi));
        unsigned h16 = *(unsigned short*)&hi, l16 = *(unsigned short*)&lo;
        int c = i >> 14, rem = i & 16383;
        int hh = rem >> 7, ww = rem & 127;
        g_xpk[c * PCH + (hh + 1) * PW + (ww + 1)] = h16 | (l16 << 16);
    } else if (b < WBLK + XBLK + PBLK) {
        int i = (b - WBLK - XBLK) * 512 + t;     // 0 .. 132095
        if (i < 256 * 516) {
            int c = i / 516, r = i - c * 516;
            int hh, ww;
            if      (r < 130)  { hh = 0;       ww = r; }
            else if (r < 260)  { hh = 129;     ww = r - 130; }
            else if (r < 388)  { hh = r - 259; ww = 0; }      // rows 1..128
            else               { hh = r - 387; ww = 129; }    // rows 1..128
            g_xpk[c * PCH + hh * PW + ww] = 0u;
        }
    } else {
        int i = (b - WBLK - XBLK - PBLK) * 512 + t;
        float bv = __ldg(&bias[i >> 12]);
        out4[i] = make_float4(bv, bv, bv, bv);
    }
}

// ---------------------------------------------------------------------------
// main: bf16x3 sparse-im2col GEMM via mma.sync m16n8k16
// Gather uses smem offset table into the zero-padded image: no address math.
// ---------------------------------------------------------------------------
__global__ __launch_bounds__(NTHR, 2) void conv_mma(
    const float* __restrict__ bias, const int* __restrict__ roi,
    float* __restrict__ out)
{
    extern __shared__ char sm[];
    __shared__ int sh_p[BN];
    const unsigned smbase = smem_u32(sm);
    int* otbl = (int*)(sm + OTBL_OFF);

    const int tid = threadIdx.x, lane = tid & 31, wid = tid >> 5;
    const int n0 = blockIdx.x * BN, m0g = blockIdx.y * BM;

    if (tid < BN) sh_p[tid] = __ldg(&roi[n0 + tid]);
    // offset table: otbl[kk] = c*PCH + di*PW + dj  (c=kk/9, s9=kk%9, di=s9/3, dj=s9%3)
    for (int i = tid; i < CK; i += NTHR) {
        int c = i / 9, s9 = i - c * 9;
        int di = s9 / 3, dj = s9 - di * 3;
        otbl[i] = c * PCH + di * PW + dj;
    }
    __syncthreads();

    const int gn = tid & 63;
    const int gkq0 = tid >> 6;            // 0..3
    const int gp = sh_p[gn];
    const unsigned* xbase = g_xpk + (gp >> 7) * PW + (gp & 127);

    const int wm = (wid >> 1) * 32, wn = (wid & 1) * 32;
    const int l8 = lane & 7;
    const unsigned a_lane_off =
        (unsigned)((wm + ((lane >> 3) & 1) * 8 + l8) * APITCH + ((lane >> 4) * 8) * 2);
    const unsigned b_lane_off =
        (unsigned)((wn + (lane >> 4) * 8 + l8) * APITCH + (((lane >> 3) & 1) * 8) * 2);

    float acc[2][4][4];
#pragma unroll
    for (int a = 0; a < 2; a++)
#pragma unroll
        for (int b = 0; b < 4; b++)
#pragma unroll
            for (int c = 0; c < 4; c++) acc[a][b][c] = 0.0f;

    unsigned pk[2][4];

    // ---- stage loaders ----
    auto issue_A = [&](int it, int st) {
        const int k0 = it * BK;
        const unsigned dst0 = smbase + st * STAGE;
#pragma unroll
        for (int r = 0; r < 4; r++) {
            int c2 = r * NTHR + tid;
            int half = c2 >> 9, m = (c2 >> 2) & 127, q = c2 & 3;
            const __nv_bfloat16* src =
                (half ? g_wlo : g_whi) + (m0g + m) * CK + k0 + q * 8;
            CPASYNC16(dst0 + half * ATILE + m * APITCH + q * 16, src);
        }
    };
    auto issue_B = [&](int it) {
        const int k0 = it * BK;
#pragma unroll
        for (int r = 0; r < 2; r++) {
            const int kq = gkq0 + r * 4;
            int4 o = *(const int4*)&otbl[k0 + kq * 4];   // warp-uniform broadcast
            pk[r][0] = __ldg(xbase + o.x);
            pk[r][1] = __ldg(xbase + o.y);
            pk[r][2] = __ldg(xbase + o.z);
            pk[r][3] = __ldg(xbase + o.w);
        }
    };
    auto store_B = [&](int st) {
        const unsigned dst0 = smbase + st * STAGE;
#pragma unroll
        for (int r = 0; r < 2; r++) {
            const int kq = gkq0 + r * 4;
            unsigned hp0 = __byte_perm(pk[r][0], pk[r][1], 0x5410);
            unsigned hp1 = __byte_perm(pk[r][2], pk[r][3], 0x5410);
            unsigned lp0 = __byte_perm(pk[r][0], pk[r][1], 0x7632);
            unsigned lp1 = __byte_perm(pk[r][2], pk[r][3], 0x7632);
            unsigned off = (unsigned)(gn * APITCH + kq * 8);
            STS64(dst0 + BH_OFF + off, hp0, hp1);
            STS64(dst0 + BL_OFF + off, lp0, lp1);
        }
    };
    auto compute = [&](int st) {
        const unsigned base = smbase + st * STAGE;
#pragma unroll
        for (int k16 = 0; k16 < 2; k16++) {
            unsigned ah[2][4], al[2][4];
#pragma unroll
            for (int mt = 0; mt < 2; mt++) {
                unsigned addr = base + a_lane_off + mt * 16 * APITCH + k16 * 32;
                LDSM4(ah[mt], addr);
                LDSM4(al[mt], addr + ATILE);
            }
            unsigned bh[2][4], bl[2][4];
#pragma unroll
            for (int np = 0; np < 2; np++) {
                unsigned addr = base + BH_OFF + b_lane_off + np * 16 * APITCH + k16 * 32;
                LDSM4(bh[np], addr);
                LDSM4(bl[np], addr + BTILE);
            }
#pragma unroll
            for (int mt = 0; mt < 2; mt++)
#pragma unroll
                for (int nt = 0; nt < 4; nt++) {
                    int np = nt >> 1, s = (nt & 1) * 2;
                    MMA16816(acc[mt][nt], ah[mt], bh[np][s], bh[np][s + 1]);
                }
#pragma unroll
            for (int mt = 0; mt < 2; mt++)
#pragma unroll
                for (int nt = 0; nt < 4; nt++) {
                    int np = nt >> 1, s = (nt & 1) * 2;
                    MMA16816(acc[mt][nt], al[mt], bh[np][s], bh[np][s + 1]);
                }
#pragma unroll
            for (int mt = 0; mt < 2; mt++)
#pragma unroll
                for (int nt = 0; nt < 4; nt++) {
                    int np = nt >> 1, s = (nt & 1) * 2;
                    MMA16816(acc[mt][nt], ah[mt], bl[np][s], bl[np][s + 1]);
                }
        }
    };

    // ---- prologue ----
    issue_A(0, 0);
    CPCOMMIT();
    issue_B(0);
    store_B(0);
    CPWAIT0();
    __syncthreads();

    // ---- mainloop (double-buffered) ----
    for (int it = 0; it < NIT; it++) {
        const int cur = it & 1, nxt = cur ^ 1;
        const bool more = (it + 1) < NIT;
        if (more) {
            issue_A(it + 1, nxt);
            CPCOMMIT();
            issue_B(it + 1);
        }
        compute(cur);
        if (more) {
            store_B(nxt);
            CPWAIT0();
        }
        __syncthreads();
    }

    // ---- epilogue: scatter acc + bias ----
#pragma unroll
    for (int mt = 0; mt < 2; mt++) {
        const int f0 = m0g + wm + mt * 16 + (lane >> 2);
        const float b0 = __ldg(&bias[f0]);
        const float b1 = __ldg(&bias[f0 + 8]);
        float* o0 = out + f0 * HW;
        float* o1 = out + (f0 + 8) * HW;
#pragma unroll
        for (int nt = 0; nt < 4; nt++) {
            const int nl = wn + nt * 8 + 2 * (lane & 3);
            const int p0 = sh_p[nl], p1 = sh_p[nl + 1];
            o0[p0] = acc[mt][nt][0] + b0;
            o0[p1] = acc[mt][nt][1] + b0;
            o1[p0] = acc[mt][nt][2] + b1;
            o1[p1] = acc[mt][nt][3] + b1;
        }
    }
}

// ---------------------------------------------------------------------------
extern "C" void kernel_launch(void* const* d_in, const int* in_sizes, int n_in,
                              void* d_out, int out_size)
{
    const float* x   = (const float*)d_in[0];
    const float* w   = (const float*)d_in[1];
    const float* b   = (const float*)d_in[2];
    const int*   roi = (const int*)d_in[3];
    float*       out = (float*)d_out;

    cudaFuncSetAttribute(conv_mma,
                         cudaFuncAttributeMaxDynamicSharedMemorySize, SMEM_BYTES);

    prep_kernel<<<WBLK + XBLK + PBLK + OBLK, 512>>>(w, x, b, (float4*)out);

    dim3 grid(NROI / BN, FDIM / BM);    // (128, 2)
    conv_mma<<<grid, NTHR, SMEM_BYTES>>>(b, roi, out);
}

// round 10
// speedup vs baseline: 1.7942x; 1.6408x over previous
#include <cuda_runtime.h>
#include <cuda_fp16.h>

// ---------------- problem constants ----------------
#define CK     2304
#define HW     16384
#define FDIM   256
#define NROI   8192
#define PW     130          // padded width/height
#define PCH    16900        // 130*130 per channel

// ---------------- GEMM config ----------------
#define BM     128
#define BN     64
#define BK     32
#define NIT    (CK / BK)        // 72
#define NTHR   256

#define APITCH 80               // bytes per smem row: 20 words -> ldmatrix conflict-free
#define ATILE  (128 * APITCH)   // 10240 (128 x 32 fp16)
#define BTILE  (64 * APITCH)    // 5120  (64 x 32 fp16)
#define B_OFF  ATILE
#define STAGE  (ATILE + BTILE)           // 15360
#define OTBL_OFF (2 * STAGE)             // offset table after the 2 stages
#define SMEM_BYTES (2 * STAGE + CK * 4)  // 30720 + 9216 = 39936 -> 2 CTAs/SM

// device scratch (allocation-free)
__device__ unsigned short g_wh[FDIM * CK];     // fp16 weights
__device__ unsigned short g_xph[256 * PCH];    // padded fp16 x

// ---------------- PTX helpers ----------------
__device__ __forceinline__ unsigned smem_u32(const void* p) {
    unsigned a;
    asm("{ .reg .u64 t; cvta.to.shared.u64 t, %1; cvt.u32.u64 %0, t; }" : "=r"(a) : "l"(p));
    return a;
}
#define LDSM4(r, a)                                                             \
    asm volatile("ldmatrix.sync.aligned.m8n8.x4.shared.b16 {%0,%1,%2,%3}, [%4];"\
        : "=r"((r)[0]), "=r"((r)[1]), "=r"((r)[2]), "=r"((r)[3]) : "r"(a))
#define MMA16816(c, a, b0, b1)                                                  \
    asm("mma.sync.aligned.m16n8k16.row.col.f32.f16.f16.f32 "                    \
        "{%0,%1,%2,%3}, {%4,%5,%6,%7}, {%8,%9}, {%0,%1,%2,%3};"                 \
        : "+f"((c)[0]), "+f"((c)[1]), "+f"((c)[2]), "+f"((c)[3])                \
        : "r"((a)[0]), "r"((a)[1]), "r"((a)[2]), "r"((a)[3]), "r"(b0), "r"(b1))
#define STS64(addr, v0, v1)                                                     \
    asm volatile("st.shared.v2.b32 [%0], {%1,%2};" :: "r"(addr), "r"(v0), "r"(v1) : "memory")
#define CPASYNC16(dst, src)                                                     \
    asm volatile("cp.async.cg.shared.global [%0], [%1], 16;" :: "r"(dst), "l"(src))
#define CPCOMMIT() asm volatile("cp.async.commit_group;" ::: "memory")
#define CPWAIT0()  asm volatile("cp.async.wait_group 0;"  ::: "memory")

// ---------------------------------------------------------------------------
// prep: w->fp16, x->padded fp16, border zero, bias fill (block-range dispatch)
// ---------------------------------------------------------------------------
#define WBLK 1152     // 589824 / 512
#define XBLK 8192     // 4194304 / 512
#define PBLK 258      // 132096 border cells / 512
#define OBLK 2048     // 1048576 float4 / 512
__global__ __launch_bounds__(512) void prep_kernel(
    const float* __restrict__ w, const float* __restrict__ x,
    const float* __restrict__ bias, float4* __restrict__ out4)
{
    int b = blockIdx.x, t = threadIdx.x;
    if (b < WBLK) {
        int i = b * 512 + t;
        __half h = __float2half_rn(w[i]);
        g_wh[i] = *(unsigned short*)&h;
    } else if (b < WBLK + XBLK) {
        int i = (b - WBLK) * 512 + t;
        __half h = __float2half_rn(x[i]);
        int c = i >> 14, rem = i & 16383;
        int hh = rem >> 7, ww = rem & 127;
        g_xph[c * PCH + (hh + 1) * PW + (ww + 1)] = *(unsigned short*)&h;
    } else if (b < WBLK + XBLK + PBLK) {
        int i = (b - WBLK - XBLK) * 512 + t;     // 0 .. 132095
        if (i < 256 * 516) {
            int c = i / 516, r = i - c * 516;
            int hh, ww;
            if      (r < 130)  { hh = 0;       ww = r; }
            else if (r < 260)  { hh = 129;     ww = r - 130; }
            else if (r < 388)  { hh = r - 259; ww = 0; }      // rows 1..128
            else               { hh = r - 387; ww = 129; }    // rows 1..128
            g_xph[c * PCH + hh * PW + ww] = 0;
        }
    } else {
        int i = (b - WBLK - XBLK - PBLK) * 512 + t;
        float bv = __ldg(&bias[i >> 12]);
        out4[i] = make_float4(bv, bv, bv, bv);
    }
}

// ---------------------------------------------------------------------------
// main: single-term fp16 sparse-im2col GEMM via mma.sync m16n8k16
// ---------------------------------------------------------------------------
__global__ __launch_bounds__(NTHR, 2) void conv_mma(
    const float* __restrict__ bias, const int* __restrict__ roi,
    float* __restrict__ out)
{
    extern __shared__ char sm[];
    __shared__ int sh_p[BN];
    const unsigned smbase = smem_u32(sm);
    int* otbl = (int*)(sm + OTBL_OFF);

    const int tid = threadIdx.x, lane = tid & 31, wid = tid >> 5;
    const int n0 = blockIdx.x * BN, m0g = blockIdx.y * BM;

    if (tid < BN) sh_p[tid] = __ldg(&roi[n0 + tid]);
    // offset table: otbl[kk] = c*PCH + di*PW + dj
    for (int i = tid; i < CK; i += NTHR) {
        int c = i / 9, s9 = i - c * 9;
        int di = s9 / 3, dj = s9 - di * 3;
        otbl[i] = c * PCH + di * PW + dj;
    }
    __syncthreads();

    const int gn = tid & 63;
    const int gkq0 = tid >> 6;            // 0..3
    const int gp = sh_p[gn];
    const unsigned short* xbase = g_xph + (gp >> 7) * PW + (gp & 127);

    const int wm = (wid >> 1) * 32, wn = (wid & 1) * 32;
    const int l8 = lane & 7;
    const unsigned a_lane_off =
        (unsigned)((wm + ((lane >> 3) & 1) * 8 + l8) * APITCH + ((lane >> 4) * 8) * 2);
    const unsigned b_lane_off =
        (unsigned)((wn + (lane >> 4) * 8 + l8) * APITCH + (((lane >> 3) & 1) * 8) * 2);

    float acc[2][4][4];
#pragma unroll
    for (int a = 0; a < 2; a++)
#pragma unroll
        for (int b = 0; b < 4; b++)
#pragma unroll
            for (int c = 0; c < 4; c++) acc[a][b][c] = 0.0f;

    unsigned short pk[2][4];

    // ---- stage loaders ----
    auto issue_A = [&](int it, int st) {
        const int k0 = it * BK;
        const unsigned dst0 = smbase + st * STAGE;
#pragma unroll
        for (int r = 0; r < 2; r++) {
            int c2 = r * NTHR + tid;           // 0..511
            int m = c2 >> 2, q = c2 & 3;
            const unsigned short* src = g_wh + (m0g + m) * CK + k0 + q * 8;
            CPASYNC16(dst0 + m * APITCH + q * 16, src);
        }
    };
    auto issue_B = [&](int it) {
        const int k0 = it * BK;
#pragma unroll
        for (int r = 0; r < 2; r++) {
            const int kq = gkq0 + r * 4;
            int4 o = *(const int4*)&otbl[k0 + kq * 4];   // warp-uniform broadcast
            pk[r][0] = __ldg(xbase + o.x);
            pk[r][1] = __ldg(xbase + o.y);
            pk[r][2] = __ldg(xbase + o.z);
            pk[r][3] = __ldg(xbase + o.w);
        }
    };
    auto store_B = [&](int st) {
        const unsigned dst0 = smbase + st * STAGE + B_OFF;
#pragma unroll
        for (int r = 0; r < 2; r++) {
            const int kq = gkq0 + r * 4;
            unsigned v0 = (unsigned)pk[r][0] | ((unsigned)pk[r][1] << 16);
            unsigned v1 = (unsigned)pk[r][2] | ((unsigned)pk[r][3] << 16);
            STS64(dst0 + (unsigned)(gn * APITCH + kq * 8), v0, v1);
        }
    };
    auto compute = [&](int st) {
        const unsigned base = smbase + st * STAGE;
#pragma unroll
        for (int k16 = 0; k16 < 2; k16++) {
            unsigned ah[2][4];
#pragma unroll
            for (int mt = 0; mt < 2; mt++)
                LDSM4(ah[mt], base + a_lane_off + mt * 16 * APITCH + k16 * 32);
            unsigned bh[2][4];
#pragma unroll
            for (int np = 0; np < 2; np++)
                LDSM4(bh[np], base + B_OFF + b_lane_off + np * 16 * APITCH + k16 * 32);
#pragma unroll
            for (int mt = 0; mt < 2; mt++)
#pragma unroll
                for (int nt = 0; nt < 4; nt++) {
                    int np = nt >> 1, s = (nt & 1) * 2;
                    MMA16816(acc[mt][nt], ah[mt], bh[np][s], bh[np][s + 1]);
                }
        }
    };

    // ---- prologue ----
    issue_A(0, 0);
    CPCOMMIT();
    issue_B(0);
    store_B(0);
    CPWAIT0();
    __syncthreads();

    // ---- mainloop (double-buffered) ----
    for (int it = 0; it < NIT; it++) {
        const int cur = it & 1, nxt = cur ^ 1;
        const bool more = (it + 1) < NIT;
        if (more) {
            issue_A(it + 1, nxt);
            CPCOMMIT();
            issue_B(it + 1);
        }
        compute(cur);
        if (more) {
            store_B(nxt);
            CPWAIT0();
        }
        __syncthreads();
    }

    // ---- epilogue: scatter acc + bias ----
#pragma unroll
    for (int mt = 0; mt < 2; mt++) {
        const int f0 = m0g + wm + mt * 16 + (lane >> 2);
        const float b0 = __ldg(&bias[f0]);
        const float b1 = __ldg(&bias[f0 + 8]);
        float* o0 = out + f0 * HW;
        float* o1 = out + (f0 + 8) * HW;
#pragma unroll
        for (int nt = 0; nt < 4; nt++) {
            const int nl = wn + nt * 8 + 2 * (lane & 3);
            const int p0 = sh_p[nl], p1 = sh_p[nl + 1];
            o0[p0] = acc[mt][nt][0] + b0;
            o0[p1] = acc[mt][nt][1] + b0;
            o1[p0] = acc[mt][nt][2] + b1;
            o1[p1] = acc[mt][nt][3] + b1;
        }
    }
}

// ---------------------------------------------------------------------------
extern "C" void kernel_launch(void* const* d_in, const int* in_sizes, int n_in,
                              void* d_out, int out_size)
{
    const float* x   = (const float*)d_in[0];
    const float* w   = (const float*)d_in[1];
    const float* b   = (const float*)d_in[2];
    const int*   roi = (const int*)d_in[3];
    float*       out = (float*)d_out;

    cudaFuncSetAttribute(conv_mma,
                         cudaFuncAttributeMaxDynamicSharedMemorySize, SMEM_BYTES);

    prep_kernel<<<WBLK + XBLK + PBLK + OBLK, 512>>>(w, x, b, (float4*)out);

    dim3 grid(NROI / BN, FDIM / BM);    // (128, 2)
    conv_mma<<<grid, NTHR, SMEM_BYTES>>>(b, roi, out);
}

// round 11
// speedup vs baseline: 1.8919x; 1.0545x over previous
#include <cuda_runtime.h>
#include <cuda_fp16.h>

// ---------------- problem constants ----------------
#define CK     2304
#define HW     16384
#define FDIM   256
#define NROI   8192
#define PW     130          // padded width/height
#define PCH    16900        // 130*130 per channel

// ---------------- GEMM config ----------------
#define BM     128
#define BN     64
#define BK     64
#define NIT    (CK / BK)        // 36
#define NTHR   256

#define APITCH 144              // 128B data + 16B pad; 36-word row stride -> LDSM conflict-free
#define ATILE  (128 * APITCH)   // 18432 (128 x 64 fp16)
#define BTILE  (64 * APITCH)    // 9216  (64 x 64 fp16)
#define B_OFF  ATILE
#define STAGE  (ATILE + BTILE)           // 27648
#define OTBL_OFF (2 * STAGE)             // 55296
#define SMEM_BYTES (2 * STAGE + CK * 4)  // 64512 -> 2 CTAs/SM (129 KB)

// device scratch (allocation-free)
__device__ unsigned short g_wh[FDIM * CK];     // fp16 weights
__device__ unsigned short g_xph[256 * PCH];    // padded fp16 x

// ---------------- PTX helpers ----------------
__device__ __forceinline__ unsigned smem_u32(const void* p) {
    unsigned a;
    asm("{ .reg .u64 t; cvta.to.shared.u64 t, %1; cvt.u32.u64 %0, t; }" : "=r"(a) : "l"(p));
    return a;
}
#define LDSM4(r, a)                                                             \
    asm volatile("ldmatrix.sync.aligned.m8n8.x4.shared.b16 {%0,%1,%2,%3}, [%4];"\
        : "=r"((r)[0]), "=r"((r)[1]), "=r"((r)[2]), "=r"((r)[3]) : "r"(a))
#define MMA16816(c, a, b0, b1)                                                  \
    asm("mma.sync.aligned.m16n8k16.row.col.f32.f16.f16.f32 "                    \
        "{%0,%1,%2,%3}, {%4,%5,%6,%7}, {%8,%9}, {%0,%1,%2,%3};"                 \
        : "+f"((c)[0]), "+f"((c)[1]), "+f"((c)[2]), "+f"((c)[3])                \
        : "r"((a)[0]), "r"((a)[1]), "r"((a)[2]), "r"((a)[3]), "r"(b0), "r"(b1))
#define STS64(addr, v0, v1)                                                     \
    asm volatile("st.shared.v2.b32 [%0], {%1,%2};" :: "r"(addr), "r"(v0), "r"(v1) : "memory")
#define CPASYNC16(dst, src)                                                     \
    asm volatile("cp.async.cg.shared.global [%0], [%1], 16;" :: "r"(dst), "l"(src))
#define CPCOMMIT() asm volatile("cp.async.commit_group;" ::: "memory")
#define CPWAIT0()  asm volatile("cp.async.wait_group 0;"  ::: "memory")

// ---------------------------------------------------------------------------
// prep: w->fp16, x->padded fp16, border zero, bias fill (block-range dispatch)
// ---------------------------------------------------------------------------
#define WBLK 1152     // 589824 / 512
#define XBLK 8192     // 4194304 / 512
#define PBLK 258      // 132096 border cells / 512
#define OBLK 2048     // 1048576 float4 / 512
__global__ __launch_bounds__(512) void prep_kernel(
    const float* __restrict__ w, const float* __restrict__ x,
    const float* __restrict__ bias, float4* __restrict__ out4)
{
    int b = blockIdx.x, t = threadIdx.x;
    if (b < WBLK) {
        int i = b * 512 + t;
        __half h = __float2half_rn(w[i]);
        g_wh[i] = *(unsigned short*)&h;
    } else if (b < WBLK + XBLK) {
        int i = (b - WBLK) * 512 + t;
        __half h = __float2half_rn(x[i]);
        int c = i >> 14, rem = i & 16383;
        int hh = rem >> 7, ww = rem & 127;
        g_xph[c * PCH + (hh + 1) * PW + (ww + 1)] = *(unsigned short*)&h;
    } else if (b < WBLK + XBLK + PBLK) {
        int i = (b - WBLK - XBLK) * 512 + t;     // 0 .. 132095
        if (i < 256 * 516) {
            int c = i / 516, r = i - c * 516;
            int hh, ww;
            if      (r < 130)  { hh = 0;       ww = r; }
            else if (r < 260)  { hh = 129;     ww = r - 130; }
            else if (r < 388)  { hh = r - 259; ww = 0; }      // rows 1..128
            else               { hh = r - 387; ww = 129; }    // rows 1..128
            g_xph[c * PCH + hh * PW + ww] = 0;
        }
    } else {
        int i = (b - WBLK - XBLK - PBLK) * 512 + t;
        float bv = __ldg(&bias[i >> 12]);
        out4[i] = make_float4(bv, bv, bv, bv);
    }
}

// ---------------------------------------------------------------------------
// main: single-term fp16 sparse-im2col GEMM, BK=64, fragment-pipelined compute
// ---------------------------------------------------------------------------
__global__ __launch_bounds__(NTHR, 2) void conv_mma(
    const float* __restrict__ bias, const int* __restrict__ roi,
    float* __restrict__ out)
{
    extern __shared__ char sm[];
    __shared__ int sh_p[BN];
    const unsigned smbase = smem_u32(sm);
    int* otbl = (int*)(sm + OTBL_OFF);

    const int tid = threadIdx.x, lane = tid & 31, wid = tid >> 5;
    const int n0 = blockIdx.x * BN, m0g = blockIdx.y * BM;

    if (tid < BN) sh_p[tid] = __ldg(&roi[n0 + tid]);
    for (int i = tid; i < CK; i += NTHR) {
        int c = i / 9, s9 = i - c * 9;
        int di = s9 / 3, dj = s9 - di * 3;
        otbl[i] = c * PCH + di * PW + dj;
    }
    __syncthreads();

    const int gn = tid & 63;
    const int gkq0 = tid >> 6;            // 0..3
    const int gp = sh_p[gn];
    const unsigned short* xbase = g_xph + (gp >> 7) * PW + (gp & 127);

    const int wm = (wid >> 1) * 32, wn = (wid & 1) * 32;
    const int l8 = lane & 7;
    const unsigned a_lane_off =
        (unsigned)((wm + ((lane >> 3) & 1) * 8 + l8) * APITCH + ((lane >> 4) * 8) * 2);
    const unsigned b_lane_off =
        (unsigned)((wn + (lane >> 4) * 8 + l8) * APITCH + (((lane >> 3) & 1) * 8) * 2);

    float acc[2][4][4];
#pragma unroll
    for (int a = 0; a < 2; a++)
#pragma unroll
        for (int b = 0; b < 4; b++)
#pragma unroll
            for (int c = 0; c < 4; c++) acc[a][b][c] = 0.0f;

    unsigned short pk[4][4];

    // ---- stage loaders ----
    auto issue_A = [&](int it, int st) {
        const int k0 = it * BK;
        const unsigned dst0 = smbase + st * STAGE;
#pragma unroll
        for (int r = 0; r < 4; r++) {
            int c2 = r * NTHR + tid;           // 0..1023
            int m = c2 >> 3, q = c2 & 7;
            const unsigned short* src = g_wh + (m0g + m) * CK + k0 + q * 8;
            CPASYNC16(dst0 + m * APITCH + q * 16, src);
        }
    };
    auto issue_B = [&](int it) {
        const int k0 = it * BK;
#pragma unroll
        for (int r = 0; r < 4; r++) {
            const int kq = gkq0 + r * 4;       // 0..15
            int4 o = *(const int4*)&otbl[k0 + kq * 4];   // warp-uniform broadcast
            pk[r][0] = __ldg(xbase + o.x);
            pk[r][1] = __ldg(xbase + o.y);
            pk[r][2] = __ldg(xbase + o.z);
            pk[r][3] = __ldg(xbase + o.w);
        }
    };
    auto store_B = [&](int st) {
        const unsigned dst0 = smbase + st * STAGE + B_OFF;
#pragma unroll
        for (int r = 0; r < 4; r++) {
            const int kq = gkq0 + r * 4;
            unsigned v0 = (unsigned)pk[r][0] | ((unsigned)pk[r][1] << 16);
            unsigned v1 = (unsigned)pk[r][2] | ((unsigned)pk[r][3] << 16);
            STS64(dst0 + (unsigned)(gn * APITCH + kq * 8), v0, v1);
        }
    };
    // fragment-pipelined compute over 4 k16 sub-blocks
    auto compute = [&](int st) {
        const unsigned base = smbase + st * STAGE;
        unsigned ah[2][2][4], bh[2][2][4];
        auto load_frags = [&](int k16, int buf) {
#pragma unroll
            for (int mt = 0; mt < 2; mt++)
                LDSM4(ah[buf][mt], base + a_lane_off + mt * 16 * APITCH + k16 * 32);
#pragma unroll
            for (int np = 0; np < 2; np++)
                LDSM4(bh[buf][np], base + B_OFF + b_lane_off + np * 16 * APITCH + k16 * 32);
        };
        load_frags(0, 0);
#pragma unroll
        for (int k16 = 0; k16 < 4; k16++) {
            const int cb = k16 & 1;
            if (k16 < 3) load_frags(k16 + 1, cb ^ 1);
#pragma unroll
            for (int mt = 0; mt < 2; mt++)
#pragma unroll
                for (int nt = 0; nt < 4; nt++) {
                    int np = nt >> 1, s = (nt & 1) * 2;
                    MMA16816(acc[mt][nt], ah[cb][mt], bh[cb][np][s], bh[cb][np][s + 1]);
                }
        }
    };

    // ---- prologue ----
    issue_A(0, 0);
    CPCOMMIT();
    issue_B(0);
    store_B(0);
    CPWAIT0();
    __syncthreads();

    // ---- mainloop (double-buffered) ----
    for (int it = 0; it < NIT; it++) {
        const int cur = it & 1, nxt = cur ^ 1;
        const bool more = (it + 1) < NIT;
        if (more) {
            issue_A(it + 1, nxt);
            CPCOMMIT();
            issue_B(it + 1);
        }
        compute(cur);
        if (more) {
            store_B(nxt);
            CPWAIT0();
        }
        __syncthreads();
    }

    // ---- epilogue: scatter acc + bias ----
#pragma unroll
    for (int mt = 0; mt < 2; mt++) {
        const int f0 = m0g + wm + mt * 16 + (lane >> 2);
        const float b0 = __ldg(&bias[f0]);
        const float b1 = __ldg(&bias[f0 + 8]);
        float* o0 = out + f0 * HW;
        float* o1 = out + (f0 + 8) * HW;
#pragma unroll
        for (int nt = 0; nt < 4; nt++) {
            const int nl = wn + nt * 8 + 2 * (lane & 3);
            const int p0 = sh_p[nl], p1 = sh_p[nl + 1];
            o0[p0] = acc[mt][nt][0] + b0;
            o0[p1] = acc[mt][nt][1] + b0;
            o1[p0] = acc[mt][nt][2] + b1;
            o1[p1] = acc[mt][nt][3] + b1;
        }
    }
}

// ---------------------------------------------------------------------------
extern "C" void kernel_launch(void* const* d_in, const int* in_sizes, int n_in,
                              void* d_out, int out_size)
{
    const float* x   = (const float*)d_in[0];
    const float* w   = (const float*)d_in[1];
    const float* b   = (const float*)d_in[2];
    const int*   roi = (const int*)d_in[3];
    float*       out = (float*)d_out;

    cudaFuncSetAttribute(conv_mma,
                         cudaFuncAttributeMaxDynamicSharedMemorySize, SMEM_BYTES);

    prep_kernel<<<WBLK + XBLK + PBLK + OBLK, 512>>>(w, x, b, (float4*)out);

    dim3 grid(NROI / BN, FDIM / BM);    // (128, 2)
    conv_mma<<<grid, NTHR, SMEM_BYTES>>>(b, roi, out);
}

// round 12
// speedup vs baseline: 1.9285x; 1.0194x over previous
#include <cuda_runtime.h>
#include <cuda_fp16.h>

// ---------------- problem constants ----------------
#define CK     2304
#define HW     16384
#define FDIM   256
#define NROI   8192
#define PW     130          // padded width/height
#define PCH    16900        // 130*130 per channel

// ---------------- GEMM config ----------------
#define BM     128
#define BN     64
#define BK     64
#define NIT    (CK / BK)        // 36
#define NTHR   256

#define APITCH 144              // 128B data + 16B pad; LDSM conflict-free
#define ATILE  (128 * APITCH)   // 18432 (128 x 64 fp16)
#define BTILE  (64 * APITCH)    // 9216  (64 x 64 fp16)
#define B_OFF  ATILE
#define STAGE  (ATILE + BTILE)           // 27648
#define SMEM_BYTES (2 * STAGE)           // 55296 -> 3 CTAs/SM (166 KB)

// device scratch (allocation-free)
__device__ unsigned short g_wh[FDIM * CK];     // fp16 weights
__device__ unsigned short g_xph[256 * PCH];    // padded fp16 x
__device__ int            g_otbl[CK];          // im2col offsets

// ---------------- PTX helpers ----------------
__device__ __forceinline__ unsigned smem_u32(const void* p) {
    unsigned a;
    asm("{ .reg .u64 t; cvta.to.shared.u64 t, %1; cvt.u32.u64 %0, t; }" : "=r"(a) : "l"(p));
    return a;
}
#define LDSM4(r, a)                                                             \
    asm volatile("ldmatrix.sync.aligned.m8n8.x4.shared.b16 {%0,%1,%2,%3}, [%4];"\
        : "=r"((r)[0]), "=r"((r)[1]), "=r"((r)[2]), "=r"((r)[3]) : "r"(a))
#define MMA16816(c, a, b0, b1)                                                  \
    asm("mma.sync.aligned.m16n8k16.row.col.f32.f16.f16.f32 "                    \
        "{%0,%1,%2,%3}, {%4,%5,%6,%7}, {%8,%9}, {%0,%1,%2,%3};"                 \
        : "+f"((c)[0]), "+f"((c)[1]), "+f"((c)[2]), "+f"((c)[3])                \
        : "r"((a)[0]), "r"((a)[1]), "r"((a)[2]), "r"((a)[3]), "r"(b0), "r"(b1))
#define STS64(addr, v0, v1)                                                     \
    asm volatile("st.shared.v2.b32 [%0], {%1,%2};" :: "r"(addr), "r"(v0), "r"(v1) : "memory")
#define CPASYNC16(dst, src)                                                     \
    asm volatile("cp.async.cg.shared.global [%0], [%1], 16;" :: "r"(dst), "l"(src))
#define CPCOMMIT() asm volatile("cp.async.commit_group;" ::: "memory")
#define CPWAIT0()  asm volatile("cp.async.wait_group 0;"  ::: "memory")

// ---------------------------------------------------------------------------
// prep: w->fp16, x->padded fp16, border zero, bias fill, offset table
// ---------------------------------------------------------------------------
#define WBLK 1152     // 589824 / 512
#define XBLK 8192     // 4194304 / 512
#define PBLK 258      // 132096 border cells / 512
#define OBLK 2048     // 1048576 float4 / 512
#define TBLK 5        // 2304 offsets / 512
__global__ __launch_bounds__(512) void prep_kernel(
    const float* __restrict__ w, const float* __restrict__ x,
    const float* __restrict__ bias, float4* __restrict__ out4)
{
    int b = blockIdx.x, t = threadIdx.x;
    if (b < WBLK) {
        int i = b * 512 + t;
        __half h = __float2half_rn(w[i]);
        g_wh[i] = *(unsigned short*)&h;
    } else if (b < WBLK + XBLK) {
        int i = (b - WBLK) * 512 + t;
        __half h = __float2half_rn(x[i]);
        int c = i >> 14, rem = i & 16383;
        int hh = rem >> 7, ww = rem & 127;
        g_xph[c * PCH + (hh + 1) * PW + (ww + 1)] = *(unsigned short*)&h;
    } else if (b < WBLK + XBLK + PBLK) {
        int i = (b - WBLK - XBLK) * 512 + t;     // 0 .. 132095
        if (i < 256 * 516) {
            int c = i / 516, r = i - c * 516;
            int hh, ww;
            if      (r < 130)  { hh = 0;       ww = r; }
            else if (r < 260)  { hh = 129;     ww = r - 130; }
            else if (r < 388)  { hh = r - 259; ww = 0; }      // rows 1..128
            else               { hh = r - 387; ww = 129; }    // rows 1..128
            g_xph[c * PCH + hh * PW + ww] = 0;
        }
    } else if (b < WBLK + XBLK + PBLK + OBLK) {
        int i = (b - WBLK - XBLK - PBLK) * 512 + t;
        float bv = __ldg(&bias[i >> 12]);
        out4[i] = make_float4(bv, bv, bv, bv);
    } else {
        int i = (b - WBLK - XBLK - PBLK - OBLK) * 512 + t;
        if (i < CK) {
            int c = i / 9, s9 = i - c * 9;
            int di = s9 / 3, dj = s9 - di * 3;
            g_otbl[i] = c * PCH + di * PW + dj;
        }
    }
}

// ---------------------------------------------------------------------------
// main: single-term fp16 sparse-im2col GEMM, BK=64, 3 CTAs/SM
// ---------------------------------------------------------------------------
__global__ __launch_bounds__(NTHR, 3) void conv_mma(
    const float* __restrict__ bias, const int* __restrict__ roi,
    float* __restrict__ out)
{
    extern __shared__ char sm[];
    __shared__ int sh_p[BN];
    const unsigned smbase = smem_u32(sm);

    const int tid = threadIdx.x, lane = tid & 31, wid = tid >> 5;
    const int n0 = blockIdx.x * BN, m0g = blockIdx.y * BM;

    if (tid < BN) sh_p[tid] = __ldg(&roi[n0 + tid]);
    __syncthreads();

    const int gn = tid & 63;
    const int gkq0 = tid >> 6;            // 0..3
    const int gp = sh_p[gn];
    const unsigned short* xbase = g_xph + (gp >> 7) * PW + (gp & 127);

    const int wm = (wid >> 1) * 32, wn = (wid & 1) * 32;
    const int l8 = lane & 7;
    const unsigned a_lane_off =
        (unsigned)((wm + ((lane >> 3) & 1) * 8 + l8) * APITCH + ((lane >> 4) * 8) * 2);
    const unsigned b_lane_off =
        (unsigned)((wn + (lane >> 4) * 8 + l8) * APITCH + (((lane >> 3) & 1) * 8) * 2);

    float acc[2][4][4];
#pragma unroll
    for (int a = 0; a < 2; a++)
#pragma unroll
        for (int b = 0; b < 4; b++)
#pragma unroll
            for (int c = 0; c < 4; c++) acc[a][b][c] = 0.0f;

    unsigned short pk[4][4];

    // ---- stage loaders ----
    auto issue_A = [&](int it, int st) {
        const int k0 = it * BK;
        const unsigned dst0 = smbase + st * STAGE;
#pragma unroll
        for (int r = 0; r < 4; r++) {
            int c2 = r * NTHR + tid;           // 0..1023
            int m = c2 >> 3, q = c2 & 7;
            const unsigned short* src = g_wh + (m0g + m) * CK + k0 + q * 8;
            CPASYNC16(dst0 + m * APITCH + q * 16, src);
        }
    };
    auto issue_B = [&](int it) {
        const int k0 = it * BK;
#pragma unroll
        for (int r = 0; r < 4; r++) {
            const int kq = gkq0 + r * 4;       // 0..15
            int4 o = *(const int4*)&g_otbl[k0 + kq * 4];   // warp-uniform, L1-hit
            pk[r][0] = __ldg(xbase + o.x);
            pk[r][1] = __ldg(xbase + o.y);
            pk[r][2] = __ldg(xbase + o.z);
            pk[r][3] = __ldg(xbase + o.w);
        }
    };
    auto store_B = [&](int st) {
        const unsigned dst0 = smbase + st * STAGE + B_OFF;
#pragma unroll
        for (int r = 0; r < 4; r++) {
            const int kq = gkq0 + r * 4;
            unsigned v0 = (unsigned)pk[r][0] | ((unsigned)pk[r][1] << 16);
            unsigned v1 = (unsigned)pk[r][2] | ((unsigned)pk[r][3] << 16);
            STS64(dst0 + (unsigned)(gn * APITCH + kq * 8), v0, v1);
        }
    };
    auto compute = [&](int st) {
        const unsigned base = smbase + st * STAGE;
#pragma unroll
        for (int k16 = 0; k16 < 4; k16++) {
            unsigned ah[2][4], bh[2][4];
#pragma unroll
            for (int mt = 0; mt < 2; mt++)
                LDSM4(ah[mt], base + a_lane_off + mt * 16 * APITCH + k16 * 32);
#pragma unroll
            for (int np = 0; np < 2; np++)
                LDSM4(bh[np], base + B_OFF + b_lane_off + np * 16 * APITCH + k16 * 32);
#pragma unroll
            for (int mt = 0; mt < 2; mt++)
#pragma unroll
                for (int nt = 0; nt < 4; nt++) {
                    int np = nt >> 1, s = (nt & 1) * 2;
                    MMA16816(acc[mt][nt], ah[mt], bh[np][s], bh[np][s + 1]);
                }
        }
    };

    // ---- prologue ----
    issue_A(0, 0);
    CPCOMMIT();
    issue_B(0);
    store_B(0);
    CPWAIT0();
    __syncthreads();

    // ---- mainloop (double-buffered) ----
    for (int it = 0; it < NIT; it++) {
        const int cur = it & 1, nxt = cur ^ 1;
        const bool more = (it + 1) < NIT;
        if (more) {
            issue_A(it + 1, nxt);
            CPCOMMIT();
            issue_B(it + 1);
        }
        compute(cur);
        if (more) {
            store_B(nxt);
            CPWAIT0();
        }
        __syncthreads();
    }

    // ---- epilogue: scatter acc + bias ----
#pragma unroll
    for (int mt = 0; mt < 2; mt++) {
        const int f0 = m0g + wm + mt * 16 + (lane >> 2);
        const float b0 = __ldg(&bias[f0]);
        const float b1 = __ldg(&bias[f0 + 8]);
        float* o0 = out + f0 * HW;
        float* o1 = out + (f0 + 8) * HW;
#pragma unroll
        for (int nt = 0; nt < 4; nt++) {
            const int nl = wn + nt * 8 + 2 * (lane & 3);
            const int p0 = sh_p[nl], p1 = sh_p[nl + 1];
            o0[p0] = acc[mt][nt][0] + b0;
            o0[p1] = acc[mt][nt][1] + b0;
            o1[p0] = acc[mt][nt][2] + b1;
            o1[p1] = acc[mt][nt][3] + b1;
        }
    }
}

// ---------------------------------------------------------------------------
extern "C" void kernel_launch(void* const* d_in, const int* in_sizes, int n_in,
                              void* d_out, int out_size)
{
    const float* x   = (const float*)d_in[0];
    const float* w   = (const float*)d_in[1];
    const float* b   = (const float*)d_in[2];
    const int*   roi = (const int*)d_in[3];
    float*       out = (float*)d_out;

    cudaFuncSetAttribute(conv_mma,
                         cudaFuncAttributeMaxDynamicSharedMemorySize, SMEM_BYTES);

    prep_kernel<<<WBLK + XBLK + PBLK + OBLK + TBLK, 512>>>(w, x, b, (float4*)out);

    dim3 grid(NROI / BN, FDIM / BM);    // (128, 2)
    conv_mma<<<grid, NTHR, SMEM_BYTES>>>(b, roi, out);
}